// round 13
// baseline (speedup 1.0000x reference)
#include <cuda_runtime.h>
#include <cuda_fp16.h>
#include <cstdint>

#define B_   256
#define P_   196
#define ENC_ 2048
#define DEC_ 512
#define ATT_ 512
#define M_TOT (B_*P_)

// split: chunk1 = 192 batches (588 m-tiles, 1176 CTAs = 3.97 waves),
//        chunk2 =  64 batches (196 m-tiles,  392 CTAs)
#define B_SPLIT 192
#define MT1 588
#define MT2 196

// ---------------- scratch (__device__ globals; no cudaMalloc allowed) ------
__device__ float  g_c4[4*B_*ATT_];   // att2 split-K partials (write-only, no zero)
__device__ float  g_attp[2*M_TOT];   // per-n-half logit partials (write-only)
__device__ __half g_Wth[ATT_*ENC_];  // W_enc^T fp16: [n][k] (2 MB)

// ---------------------------------------------------------------------------
__device__ __forceinline__ uint32_t smem_u32(const void* p) {
    uint32_t a;
    asm("{ .reg .u64 t; cvta.to.shared.u64 t, %1; cvt.u32.u64 %0, t; }" : "=r"(a) : "l"(p));
    return a;
}
__device__ __forceinline__ void cp16(uint32_t dst, const void* src) {
    asm volatile("cp.async.cg.shared.global [%0], [%1], 16;" :: "r"(dst), "l"(src));
}
#define CP_COMMIT() asm volatile("cp.async.commit_group;" ::: "memory")
#define CP_WAIT2()  asm volatile("cp.async.wait_group 2;" ::: "memory")

// ---------------------------------------------------------------------------
// Kernel 0: transpose+convert W_enc [ENC,ATT] fp32 -> g_Wth [ATT][ENC] fp16
// ---------------------------------------------------------------------------
__global__ void k_transpose(const float* __restrict__ W) {
    __shared__ float t[32][33];
    int k0 = blockIdx.x * 32, n0 = blockIdx.y * 32;
    int x = threadIdx.x, y = threadIdx.y;   // 32 x 8
#pragma unroll
    for (int j = 0; j < 32; j += 8)
        t[y + j][x] = W[(size_t)(k0 + y + j) * ATT_ + n0 + x];
    __syncthreads();
#pragma unroll
    for (int j = 0; j < 32; j += 8)
        g_Wth[(size_t)(n0 + y + j) * ENC_ + k0 + x] = __float2half_rn(t[x][y + j]);
}

// ---------------------------------------------------------------------------
// Kernel 1: split-K att2 partials: g_c4[kz][b][a] = dec[b,k0:+128]@W_dec[k0:+128,a]
//   (+ biases on kz==0 slice).  No atomics, no zeroing.
// ---------------------------------------------------------------------------
__global__ void k_att2(const float* __restrict__ dec,
                       const float* __restrict__ W_dec,
                       const float* __restrict__ b_dec,
                       const float* __restrict__ b_enc) {
    int b0 = blockIdx.x * 4;
    int kz = blockIdx.y;
    int k0 = kz * 128;
    int tid = threadIdx.x;            // 512
    __shared__ float sdec[4][128];
    {
        int bb = tid >> 7, e = tid & 127;
        sdec[bb][e] = dec[(b0 + bb)*DEC_ + k0 + e];
    }
    __syncthreads();
    int a = tid;
    float acc[4] = {0.f, 0.f, 0.f, 0.f};
#pragma unroll 4
    for (int e = 0; e < 128; e++) {
        float w = W_dec[(size_t)(k0 + e)*ATT_ + a];
#pragma unroll
        for (int bb = 0; bb < 4; bb++) acc[bb] += sdec[bb][e] * w;
    }
    float bias = (kz == 0) ? (b_dec[a] + b_enc[a]) : 0.f;
    float* dst = g_c4 + (size_t)kz*B_*ATT_;
#pragma unroll
    for (int bb = 0; bb < 4; bb++)
        dst[(b0+bb)*ATT_ + a] = acc[bb] + bias;
}

// ---------------------------------------------------------------------------
// Kernel 2: fp16 mma.sync fused logits GEMM (R11 mainloop, mbase-offset grid)
//   CTA 64(M) x 256(N), BK=32, 4-stage, 8 warps x warptile 64x32, 2 CTAs/SM.
//   Epilogue writes g_attp[n_half][m] with plain stores (no atomics).
// ---------------------------------------------------------------------------
#define BM 64
#define BN 256
#define BK 32
#define NK (ENC_/BK)          // 64
#define NSTG 4
#define ROWB 80               // bytes per smem row (32 halves + 8 pad)
#define A_STG (BM*ROWB)       // 5120
#define B_STG (BN*ROWB)       // 20480
#define OFF_A    0
#define OFF_B    (NSTG*A_STG)                   // 20480
#define OFF_CS   (OFF_B + NSTG*B_STG)           // 102400
#define OFF_WS   (OFF_CS + 2*BN*4)              // 104448
#define OFF_SRED (OFF_WS + BN*4)                // 105472
#define SMEM_BYTES (OFF_SRED + BM*8*4)          // 107520

__device__ __forceinline__ void a_ldg(const float* __restrict__ enc, int m0, int kt,
                                      int tid, float4& l0, float4& l1) {
    int row = tid >> 2, c = tid & 3;
    const float* src = enc + (size_t)(m0 + row)*ENC_ + kt*BK + c*8;
    l0 = *(const float4*)src;
    l1 = *(const float4*)(src + 4);
}
__device__ __forceinline__ void a_sts(char* smem, int stg, int tid,
                                      const float4& l0, const float4& l1) {
    int row = tid >> 2, c = tid & 3;
    __half2 h[4];
    h[0] = __floats2half2_rn(l0.x, l0.y);
    h[1] = __floats2half2_rn(l0.z, l0.w);
    h[2] = __floats2half2_rn(l1.x, l1.y);
    h[3] = __floats2half2_rn(l1.z, l1.w);
    *(uint4*)(smem + OFF_A + stg*A_STG + row*ROWB + c*16) = *(uint4*)h;
}
__device__ __forceinline__ void b_load(uint32_t smb, int n0, int kt, int stg, int tid) {
    int k0 = kt * BK;
#pragma unroll
    for (int j = 0; j < 4; j++) {
        int i = tid + j*256;
        int row = i >> 2, c = i & 3;
        cp16(smb + OFF_B + stg*B_STG + row*ROWB + c*16,
             g_Wth + (size_t)(n0 + row)*ENC_ + k0 + c*8);
    }
}

__global__ void __launch_bounds__(256, 2)
k_gemm(const float* __restrict__ enc, const float* __restrict__ W_full, int mbase) {
    extern __shared__ __align__(16) char smem[];
    uint32_t smb = smem_u32(smem);
    float* cs   = (float*)(smem + OFF_CS);    // [2][BN]
    float* ws   = (float*)(smem + OFF_WS);    // [BN]
    float* sred = (float*)(smem + OFF_SRED);  // [BM][8]

    int tid = threadIdx.x;
    int wn = tid >> 5, lane = tid & 31;       // 8 warps across N
    int g = lane >> 2, tg = lane & 3;
    int n0 = blockIdx.x * BN;                 // 0 or 256
    int m0 = mbase + blockIdx.y * BM;
    int bglob0 = m0 / P_;                     // tile spans <= 2 batches

    // epilogue constants (CTA's n-slice); sum 4 split-K partials of c
    ws[tid] = W_full[n0 + tid];
#pragma unroll
    for (int i = 0; i < 2; i++) {
        int bb = bglob0 + i; if (bb > B_-1) bb = B_-1;
        int idx = bb*ATT_ + n0 + tid;
        cs[i*BN + tid] = g_c4[idx] + g_c4[B_*ATT_ + idx]
                       + g_c4[2*B_*ATT_ + idx] + g_c4[3*B_*ATT_ + idx];
    }

    float acc[4][4][4];
#pragma unroll
    for (int a = 0; a < 4; a++)
#pragma unroll
        for (int b = 0; b < 4; b++)
#pragma unroll
            for (int c = 0; c < 4; c++) acc[a][b][c] = 0.f;

    // prologue: stages 0..2
#pragma unroll
    for (int s = 0; s < NSTG-1; s++) {
        float4 l0, l1;
        a_ldg(enc, m0, s, tid, l0, l1);
        a_sts(smem, s, tid, l0, l1);
        b_load(smb, n0, s, s, tid);
        CP_COMMIT();
    }

#pragma unroll 1
    for (int kt = 0; kt < NK; kt++) {
        CP_WAIT2();          // B stage kt landed (own view)
        __syncthreads();     // CTA visibility; iter kt-1 fully consumed
        bool pre = (kt + NSTG-1 < NK);
        int stg3 = (kt + NSTG-1) & (NSTG-1);
        float4 l0, l1;
        if (pre) {
            a_ldg(enc, m0, kt + NSTG-1, tid, l0, l1);  // long-latency, STS below
            b_load(smb, n0, kt + NSTG-1, stg3, tid);
        }
        CP_COMMIT();

        int stg = kt & (NSTG-1);
        const uint32_t* As = (const uint32_t*)(smem + OFF_A + stg*A_STG);  // stride 20 u32
        const uint32_t* Bs = (const uint32_t*)(smem + OFF_B + stg*B_STG);

#pragma unroll
        for (int kk = 0; kk < 2; kk++) {      // two k16 steps
            int kb = kk * 8;
            uint32_t af[4][4], bf[4][2];
#pragma unroll
            for (int ms = 0; ms < 4; ms++) {
                int r = ms*16 + g;
                af[ms][0] = As[ r     *20 + kb + tg    ];
                af[ms][1] = As[(r + 8)*20 + kb + tg    ];
                af[ms][2] = As[ r     *20 + kb + tg + 4];
                af[ms][3] = As[(r + 8)*20 + kb + tg + 4];
            }
#pragma unroll
            for (int ns = 0; ns < 4; ns++) {
                int n = wn*32 + ns*8 + g;
                bf[ns][0] = Bs[n*20 + kb + tg    ];
                bf[ns][1] = Bs[n*20 + kb + tg + 4];
            }
#pragma unroll
            for (int ms = 0; ms < 4; ms++)
#pragma unroll
                for (int ns = 0; ns < 4; ns++)
                    asm volatile(
                        "mma.sync.aligned.m16n8k16.row.col.f32.f16.f16.f32 "
                        "{%0,%1,%2,%3},{%4,%5,%6,%7},{%8,%9},{%0,%1,%2,%3};"
                        : "+f"(acc[ms][ns][0]), "+f"(acc[ms][ns][1]),
                          "+f"(acc[ms][ns][2]), "+f"(acc[ms][ns][3])
                        : "r"(af[ms][0]), "r"(af[ms][1]), "r"(af[ms][2]), "r"(af[ms][3]),
                          "r"(bf[ns][0]), "r"(bf[ns][1]));
            if (kk == 0 && pre) a_sts(smem, stg3, tid, l0, l1);
        }
    }

    // fused epilogue: +c, relu, *W_full, reduce over this CTA's 256 cols
#pragma unroll
    for (int ms = 0; ms < 4; ms++) {
#pragma unroll
        for (int h = 0; h < 2; h++) {
            int row = ms*16 + h*8 + g;
            int m = m0 + row;
            int bsel = (m / P_) - bglob0;
            const float* csr = cs + bsel*BN;
            float s = 0.f;
#pragma unroll
            for (int ns = 0; ns < 4; ns++) {
#pragma unroll
                for (int j = 0; j < 2; j++) {
                    int col = wn*32 + ns*8 + tg*2 + j;
                    float v = acc[ms][ns][h*2 + j] + csr[col];
                    s += fmaxf(v, 0.f) * ws[col];
                }
            }
            s += __shfl_xor_sync(0xffffffffu, s, 1);
            s += __shfl_xor_sync(0xffffffffu, s, 2);
            if (tg == 0) sred[row*8 + wn] = s;
        }
    }
    __syncthreads();
    if (tid < BM) {
        float s = 0.f;
#pragma unroll
        for (int w = 0; w < 8; w++) s += sred[tid*8 + w];
        g_attp[blockIdx.x*M_TOT + m0 + tid] = s;   // plain store, no atomic
    }
}

// ---------------------------------------------------------------------------
// Kernel 3: fused softmax (over P) + context GEMV (fp32 enc, HBM-bound)
//   grid (2 e-halves, nb batches starting at bbase)
// ---------------------------------------------------------------------------
__global__ void k_softctx(const float* __restrict__ enc,
                          float* __restrict__ alpha,
                          float* __restrict__ ctx, int bbase) {
    int b = bbase + blockIdx.y, t = threadIdx.x;
    __shared__ float sm[256];
    __shared__ float sal[P_];
    float x = (t < P_) ? (g_attp[b*P_ + t] + g_attp[M_TOT + b*P_ + t]) : -1e30f;
    sm[t] = x; __syncthreads();
#pragma unroll
    for (int s = 128; s > 0; s >>= 1) {
        if (t < s) sm[t] = fmaxf(sm[t], sm[t+s]);
        __syncthreads();
    }
    float mx = sm[0]; __syncthreads();
    float e = (t < P_) ? __expf(x - mx) : 0.f;
    sm[t] = e; __syncthreads();
#pragma unroll
    for (int s = 128; s > 0; s >>= 1) {
        if (t < s) sm[t] += sm[t+s];
        __syncthreads();
    }
    float inv = 1.f / sm[0];
    float av = e * inv;
    if (t < P_) {
        sal[t] = av;
        if (blockIdx.x == 0) alpha[b*P_ + t] = av;
    }
    __syncthreads();

    int e0 = blockIdx.x * 1024 + t * 4;
    const float4* base = (const float4*)(enc + (size_t)b * P_ * ENC_ + e0);
    float4 acc = make_float4(0.f, 0.f, 0.f, 0.f);
#pragma unroll 4
    for (int p = 0; p < P_; p++) {
        float a = sal[p];
        float4 v = base[p * (ENC_/4)];
        acc.x += a*v.x; acc.y += a*v.y; acc.z += a*v.z; acc.w += a*v.w;
    }
    *(float4*)(ctx + (size_t)b*ENC_ + e0) = acc;
}

// ---------------------------------------------------------------------------
extern "C" void kernel_launch(void* const* d_in, const int* in_sizes, int n_in,
                              void* d_out, int out_size) {
    const float* enc    = (const float*)d_in[0];
    const float* dec    = (const float*)d_in[1];
    const float* W_enc  = (const float*)d_in[2];
    const float* b_enc  = (const float*)d_in[3];
    const float* W_dec  = (const float*)d_in[4];
    const float* b_dec  = (const float*)d_in[5];
    const float* W_full = (const float*)d_in[6];
    (void)in_sizes; (void)n_in; (void)out_size;

    float* out   = (float*)d_out;
    float* ctx   = out;               // [B, ENC]
    float* alpha = out + B_*ENC_;     // [B, P]

    static cudaStream_t s1;
    static cudaEvent_t evFork, evA, ev1, ev2;
    static int init = 0;
    if (!init) {
        cudaFuncSetAttribute(k_gemm, cudaFuncAttributeMaxDynamicSharedMemorySize, SMEM_BYTES);
        cudaStreamCreateWithFlags(&s1, cudaStreamNonBlocking);
        cudaEventCreateWithFlags(&evFork, cudaEventDisableTiming);
        cudaEventCreateWithFlags(&evA, cudaEventDisableTiming);
        cudaEventCreateWithFlags(&ev1, cudaEventDisableTiming);
        cudaEventCreateWithFlags(&ev2, cudaEventDisableTiming);
        init = 1;
    }

    // legal capture fork: s1 enters the graph via an event from stream 0
    cudaEventRecord(evFork, 0);
    cudaStreamWaitEvent(s1, evFork, 0);

    // prep: att2 on s1 concurrent with transpose on stream 0
    k_att2<<<dim3(B_/4, 4), 512, 0, s1>>>(dec, W_dec, b_dec, b_enc);
    cudaEventRecord(evA, s1);
    k_transpose<<<dim3(ENC_/32, ATT_/32), dim3(32, 8)>>>(W_enc);
    cudaStreamWaitEvent(0, evA, 0);

    // gemm chunk 1 (192 batches, 1176 CTAs = 3.97 waves)
    k_gemm<<<dim3(2, MT1), 256, SMEM_BYTES>>>(enc, W_full, 0);
    cudaEventRecord(ev1, 0);
    // gemm chunk 2 (64 batches) on stream 0; softctx chunk 1 overlaps on s1
    k_gemm<<<dim3(2, MT2), 256, SMEM_BYTES>>>(enc, W_full, MT1*BM);
    cudaStreamWaitEvent(s1, ev1, 0);
    k_softctx<<<dim3(2, B_SPLIT), 256, 0, s1>>>(enc, alpha, ctx, 0);
    cudaEventRecord(ev2, s1);
    // softctx chunk 2 after gemm2 on stream 0
    k_softctx<<<dim3(2, B_ - B_SPLIT), 256>>>(enc, alpha, ctx, B_SPLIT);
    cudaStreamWaitEvent(0, ev2, 0);   // join s1 back into capture stream
}

// round 14
// speedup vs baseline: 1.0741x; 1.0741x over previous
#include <cuda_runtime.h>
#include <cuda_fp16.h>
#include <cstdint>

#define B_   256
#define P_   196
#define ENC_ 2048
#define DEC_ 512
#define ATT_ 512
#define M_TOT (B_*P_)

// ---------------- scratch (__device__ globals; no cudaMalloc allowed) ------
__device__ float  g_c4[4*B_*ATT_];   // att2 split-K partials (write-only, no zero)
__device__ float  g_attp[2*M_TOT];   // per-n-half logit partials (write-only)
__device__ __half g_Wth[ATT_*ENC_];  // W_enc^T fp16: [n][k] (2 MB)

// ---------------------------------------------------------------------------
__device__ __forceinline__ uint32_t smem_u32(const void* p) {
    uint32_t a;
    asm("{ .reg .u64 t; cvta.to.shared.u64 t, %1; cvt.u32.u64 %0, t; }" : "=r"(a) : "l"(p));
    return a;
}
__device__ __forceinline__ void cp16(uint32_t dst, const void* src) {
    asm volatile("cp.async.cg.shared.global [%0], [%1], 16;" :: "r"(dst), "l"(src));
}
#define CP_COMMIT() asm volatile("cp.async.commit_group;" ::: "memory")
#define CP_WAIT2()  asm volatile("cp.async.wait_group 2;" ::: "memory")

// ---------------------------------------------------------------------------
// Kernel 0: transpose+convert W_enc [ENC,ATT] fp32 -> g_Wth [ATT][ENC] fp16
// ---------------------------------------------------------------------------
__global__ void k_transpose(const float* __restrict__ W) {
    __shared__ float t[32][33];
    int k0 = blockIdx.x * 32, n0 = blockIdx.y * 32;
    int x = threadIdx.x, y = threadIdx.y;   // 32 x 8
#pragma unroll
    for (int j = 0; j < 32; j += 8)
        t[y + j][x] = W[(size_t)(k0 + y + j) * ATT_ + n0 + x];
    __syncthreads();
#pragma unroll
    for (int j = 0; j < 32; j += 8)
        g_Wth[(size_t)(n0 + y + j) * ENC_ + k0 + x] = __float2half_rn(t[x][y + j]);
}

// ---------------------------------------------------------------------------
// Kernel 1: split-K att2 partials: g_c4[kz][b][a] = dec[b,k0:+128]@W_dec[k0:+128,a]
//   (+ biases on kz==0 slice).  No atomics, no zeroing.
// ---------------------------------------------------------------------------
__global__ void k_att2(const float* __restrict__ dec,
                       const float* __restrict__ W_dec,
                       const float* __restrict__ b_dec,
                       const float* __restrict__ b_enc) {
    int b0 = blockIdx.x * 4;
    int kz = blockIdx.y;
    int k0 = kz * 128;
    int tid = threadIdx.x;            // 512
    __shared__ float sdec[4][128];
    {
        int bb = tid >> 7, e = tid & 127;
        sdec[bb][e] = dec[(b0 + bb)*DEC_ + k0 + e];
    }
    __syncthreads();
    int a = tid;
    float acc[4] = {0.f, 0.f, 0.f, 0.f};
#pragma unroll 4
    for (int e = 0; e < 128; e++) {
        float w = W_dec[(size_t)(k0 + e)*ATT_ + a];
#pragma unroll
        for (int bb = 0; bb < 4; bb++) acc[bb] += sdec[bb][e] * w;
    }
    float bias = (kz == 0) ? (b_dec[a] + b_enc[a]) : 0.f;
    float* dst = g_c4 + (size_t)kz*B_*ATT_;
#pragma unroll
    for (int bb = 0; bb < 4; bb++)
        dst[(b0+bb)*ATT_ + a] = acc[bb] + bias;
}

// ---------------------------------------------------------------------------
// Kernel 2: fp16 mma.sync fused logits GEMM (R11, single full launch, UNTOUCHED)
//   CTA 64(M) x 256(N), BK=32, 4-stage, 8 warps x warptile 64x32, 2 CTAs/SM.
// ---------------------------------------------------------------------------
#define BM 64
#define BN 256
#define BK 32
#define NK (ENC_/BK)          // 64
#define NSTG 4
#define ROWB 80               // bytes per smem row (32 halves + 8 pad)
#define A_STG (BM*ROWB)       // 5120
#define B_STG (BN*ROWB)       // 20480
#define OFF_A    0
#define OFF_B    (NSTG*A_STG)                   // 20480
#define OFF_CS   (OFF_B + NSTG*B_STG)           // 102400
#define OFF_WS   (OFF_CS + 2*BN*4)              // 104448
#define OFF_SRED (OFF_WS + BN*4)                // 105472
#define SMEM_BYTES (OFF_SRED + BM*8*4)          // 107520

__device__ __forceinline__ void a_ldg(const float* __restrict__ enc, int m0, int kt,
                                      int tid, float4& l0, float4& l1) {
    int row = tid >> 2, c = tid & 3;
    const float* src = enc + (size_t)(m0 + row)*ENC_ + kt*BK + c*8;
    l0 = *(const float4*)src;
    l1 = *(const float4*)(src + 4);
}
__device__ __forceinline__ void a_sts(char* smem, int stg, int tid,
                                      const float4& l0, const float4& l1) {
    int row = tid >> 2, c = tid & 3;
    __half2 h[4];
    h[0] = __floats2half2_rn(l0.x, l0.y);
    h[1] = __floats2half2_rn(l0.z, l0.w);
    h[2] = __floats2half2_rn(l1.x, l1.y);
    h[3] = __floats2half2_rn(l1.z, l1.w);
    *(uint4*)(smem + OFF_A + stg*A_STG + row*ROWB + c*16) = *(uint4*)h;
}
__device__ __forceinline__ void b_load(uint32_t smb, int n0, int kt, int stg, int tid) {
    int k0 = kt * BK;
#pragma unroll
    for (int j = 0; j < 4; j++) {
        int i = tid + j*256;
        int row = i >> 2, c = i & 3;
        cp16(smb + OFF_B + stg*B_STG + row*ROWB + c*16,
             g_Wth + (size_t)(n0 + row)*ENC_ + k0 + c*8);
    }
}

__global__ void __launch_bounds__(256, 2)
k_gemm(const float* __restrict__ enc, const float* __restrict__ W_full) {
    extern __shared__ __align__(16) char smem[];
    uint32_t smb = smem_u32(smem);
    float* cs   = (float*)(smem + OFF_CS);    // [2][BN]
    float* ws   = (float*)(smem + OFF_WS);    // [BN]
    float* sred = (float*)(smem + OFF_SRED);  // [BM][8]

    int tid = threadIdx.x;
    int wn = tid >> 5, lane = tid & 31;       // 8 warps across N
    int g = lane >> 2, tg = lane & 3;
    int n0 = blockIdx.x * BN;                 // 0 or 256
    int m0 = blockIdx.y * BM;
    int bglob0 = m0 / P_;                     // tile spans <= 2 batches

    // epilogue constants (CTA's n-slice); sum 4 split-K partials of c
    ws[tid] = W_full[n0 + tid];
#pragma unroll
    for (int i = 0; i < 2; i++) {
        int bb = bglob0 + i; if (bb > B_-1) bb = B_-1;
        int idx = bb*ATT_ + n0 + tid;
        cs[i*BN + tid] = g_c4[idx] + g_c4[B_*ATT_ + idx]
                       + g_c4[2*B_*ATT_ + idx] + g_c4[3*B_*ATT_ + idx];
    }

    float acc[4][4][4];
#pragma unroll
    for (int a = 0; a < 4; a++)
#pragma unroll
        for (int b = 0; b < 4; b++)
#pragma unroll
            for (int c = 0; c < 4; c++) acc[a][b][c] = 0.f;

    // prologue: stages 0..2
#pragma unroll
    for (int s = 0; s < NSTG-1; s++) {
        float4 l0, l1;
        a_ldg(enc, m0, s, tid, l0, l1);
        a_sts(smem, s, tid, l0, l1);
        b_load(smb, n0, s, s, tid);
        CP_COMMIT();
    }

#pragma unroll 1
    for (int kt = 0; kt < NK; kt++) {
        CP_WAIT2();          // B stage kt landed (own view)
        __syncthreads();     // CTA visibility; iter kt-1 fully consumed
        bool pre = (kt + NSTG-1 < NK);
        int stg3 = (kt + NSTG-1) & (NSTG-1);
        float4 l0, l1;
        if (pre) {
            a_ldg(enc, m0, kt + NSTG-1, tid, l0, l1);  // long-latency, STS below
            b_load(smb, n0, kt + NSTG-1, stg3, tid);
        }
        CP_COMMIT();

        int stg = kt & (NSTG-1);
        const uint32_t* As = (const uint32_t*)(smem + OFF_A + stg*A_STG);  // stride 20 u32
        const uint32_t* Bs = (const uint32_t*)(smem + OFF_B + stg*B_STG);

#pragma unroll
        for (int kk = 0; kk < 2; kk++) {      // two k16 steps
            int kb = kk * 8;
            uint32_t af[4][4], bf[4][2];
#pragma unroll
            for (int ms = 0; ms < 4; ms++) {
                int r = ms*16 + g;
                af[ms][0] = As[ r     *20 + kb + tg    ];
                af[ms][1] = As[(r + 8)*20 + kb + tg    ];
                af[ms][2] = As[ r     *20 + kb + tg + 4];
                af[ms][3] = As[(r + 8)*20 + kb + tg + 4];
            }
#pragma unroll
            for (int ns = 0; ns < 4; ns++) {
                int n = wn*32 + ns*8 + g;
                bf[ns][0] = Bs[n*20 + kb + tg    ];
                bf[ns][1] = Bs[n*20 + kb + tg + 4];
            }
#pragma unroll
            for (int ms = 0; ms < 4; ms++)
#pragma unroll
                for (int ns = 0; ns < 4; ns++)
                    asm volatile(
                        "mma.sync.aligned.m16n8k16.row.col.f32.f16.f16.f32 "
                        "{%0,%1,%2,%3},{%4,%5,%6,%7},{%8,%9},{%0,%1,%2,%3};"
                        : "+f"(acc[ms][ns][0]), "+f"(acc[ms][ns][1]),
                          "+f"(acc[ms][ns][2]), "+f"(acc[ms][ns][3])
                        : "r"(af[ms][0]), "r"(af[ms][1]), "r"(af[ms][2]), "r"(af[ms][3]),
                          "r"(bf[ns][0]), "r"(bf[ns][1]));
            if (kk == 0 && pre) a_sts(smem, stg3, tid, l0, l1);
        }
    }

    // fused epilogue: +c, relu, *W_full, reduce over this CTA's 256 cols
#pragma unroll
    for (int ms = 0; ms < 4; ms++) {
#pragma unroll
        for (int h = 0; h < 2; h++) {
            int row = ms*16 + h*8 + g;
            int m = m0 + row;
            int bsel = (m / P_) - bglob0;
            const float* csr = cs + bsel*BN;
            float s = 0.f;
#pragma unroll
            for (int ns = 0; ns < 4; ns++) {
#pragma unroll
                for (int j = 0; j < 2; j++) {
                    int col = wn*32 + ns*8 + tg*2 + j;
                    float v = acc[ms][ns][h*2 + j] + csr[col];
                    s += fmaxf(v, 0.f) * ws[col];
                }
            }
            s += __shfl_xor_sync(0xffffffffu, s, 1);
            s += __shfl_xor_sync(0xffffffffu, s, 2);
            if (tg == 0) sred[row*8 + wn] = s;
        }
    }
    __syncthreads();
    if (tid < BM) {
        float s = 0.f;
#pragma unroll
        for (int w = 0; w < 8; w++) s += sred[tid*8 + w];
        g_attp[blockIdx.x*M_TOT + m0 + tid] = s;   // plain store, no atomic
    }
}

// ---------------------------------------------------------------------------
// Kernel 3: fused softmax (over P) + context GEMV (fp32 enc, HBM-bound)
//   grid (2 e-halves, B); unroll 8, two independent accumulator chains.
// ---------------------------------------------------------------------------
__global__ void k_softctx(const float* __restrict__ enc,
                          float* __restrict__ alpha,
                          float* __restrict__ ctx) {
    int b = blockIdx.y, t = threadIdx.x;
    __shared__ float sm[256];
    __shared__ float sal[P_ + 4];     // padded: p loop reads up to 196+3
    float x = (t < P_) ? (g_attp[b*P_ + t] + g_attp[M_TOT + b*P_ + t]) : -1e30f;
    sm[t] = x; __syncthreads();
#pragma unroll
    for (int s = 128; s > 0; s >>= 1) {
        if (t < s) sm[t] = fmaxf(sm[t], sm[t+s]);
        __syncthreads();
    }
    float mx = sm[0]; __syncthreads();
    float e = (t < P_) ? __expf(x - mx) : 0.f;
    sm[t] = e; __syncthreads();
#pragma unroll
    for (int s = 128; s > 0; s >>= 1) {
        if (t < s) sm[t] += sm[t+s];
        __syncthreads();
    }
    float inv = 1.f / sm[0];
    float av = e * inv;
    if (t < P_) {
        sal[t] = av;
        if (blockIdx.x == 0) alpha[b*P_ + t] = av;
    }
    if (t < 4) sal[P_ + t] = 0.f;     // zero pad (196 % 4 == 0, safe anyway)
    __syncthreads();

    int e0 = blockIdx.x * 1024 + t * 4;
    const float4* base = (const float4*)(enc + (size_t)b * P_ * ENC_ + e0);
    float4 acc0 = make_float4(0.f, 0.f, 0.f, 0.f);
    float4 acc1 = make_float4(0.f, 0.f, 0.f, 0.f);
#pragma unroll 4
    for (int p = 0; p < P_; p += 2) {          // 196 even: exact
        float a0 = sal[p], a1 = sal[p+1];
        float4 v0 = base[ p    * (ENC_/4)];
        float4 v1 = base[(p+1) * (ENC_/4)];
        acc0.x += a0*v0.x; acc0.y += a0*v0.y; acc0.z += a0*v0.z; acc0.w += a0*v0.w;
        acc1.x += a1*v1.x; acc1.y += a1*v1.y; acc1.z += a1*v1.z; acc1.w += a1*v1.w;
    }
    acc0.x += acc1.x; acc0.y += acc1.y; acc0.z += acc1.z; acc0.w += acc1.w;
    *(float4*)(ctx + (size_t)b*ENC_ + e0) = acc0;
}

// ---------------------------------------------------------------------------
extern "C" void kernel_launch(void* const* d_in, const int* in_sizes, int n_in,
                              void* d_out, int out_size) {
    const float* enc    = (const float*)d_in[0];
    const float* dec    = (const float*)d_in[1];
    const float* W_enc  = (const float*)d_in[2];
    const float* b_enc  = (const float*)d_in[3];
    const float* W_dec  = (const float*)d_in[4];
    const float* b_dec  = (const float*)d_in[5];
    const float* W_full = (const float*)d_in[6];
    (void)in_sizes; (void)n_in; (void)out_size;

    float* out   = (float*)d_out;
    float* ctx   = out;               // [B, ENC]
    float* alpha = out + B_*ENC_;     // [B, P]

    static cudaStream_t s1;
    static cudaEvent_t evFork, evA;
    static int init = 0;
    if (!init) {
        cudaFuncSetAttribute(k_gemm, cudaFuncAttributeMaxDynamicSharedMemorySize, SMEM_BYTES);
        cudaStreamCreateWithFlags(&s1, cudaStreamNonBlocking);
        cudaEventCreateWithFlags(&evFork, cudaEventDisableTiming);
        cudaEventCreateWithFlags(&evA, cudaEventDisableTiming);
        init = 1;
    }

    // legal capture fork (R13-verified): att2 on s1 concurrent with transpose on s0
    cudaEventRecord(evFork, 0);
    cudaStreamWaitEvent(s1, evFork, 0);
    k_att2<<<dim3(B_/4, 4), 512, 0, s1>>>(dec, W_dec, b_dec, b_enc);
    cudaEventRecord(evA, s1);
    k_transpose<<<dim3(ENC_/32, ATT_/32), dim3(32, 8)>>>(W_enc);
    cudaStreamWaitEvent(0, evA, 0);   // join before gemm

    // GEMM: one untouched full launch (5.3 waves, best measured packing)
    k_gemm<<<dim3(ATT_/BN, M_TOT/BM), 256, SMEM_BYTES>>>(enc, W_full);
    // softmax+context: one launch after gemm
    k_softctx<<<dim3(2, B_), 256>>>(enc, alpha, ctx);
}

// round 15
// speedup vs baseline: 1.0786x; 1.0042x over previous
#include <cuda_runtime.h>
#include <cuda_fp16.h>
#include <cstdint>

#define B_   256
#define P_   196
#define ENC_ 2048
#define DEC_ 512
#define ATT_ 512
#define M_TOT (B_*P_)

// ---------------- scratch (__device__ globals; no cudaMalloc allowed) ------
__device__ float  g_c4[4*B_*ATT_];   // att2 split-K partials (write-only, no zero)
__device__ float  g_attp[2*M_TOT];   // per-n-half logit partials (write-only)
__device__ __half g_Wth[ATT_*ENC_];  // W_enc^T fp16: [n][k] (2 MB)

// ---------------------------------------------------------------------------
__device__ __forceinline__ uint32_t smem_u32(const void* p) {
    uint32_t a;
    asm("{ .reg .u64 t; cvta.to.shared.u64 t, %1; cvt.u32.u64 %0, t; }" : "=r"(a) : "l"(p));
    return a;
}
__device__ __forceinline__ void cp16(uint32_t dst, const void* src) {
    asm volatile("cp.async.cg.shared.global [%0], [%1], 16;" :: "r"(dst), "l"(src));
}
#define CP_COMMIT() asm volatile("cp.async.commit_group;" ::: "memory")
#define CP_WAIT2()  asm volatile("cp.async.wait_group 2;" ::: "memory")

// ---------------------------------------------------------------------------
// Kernel 0: transpose+convert W_enc [ENC,ATT] fp32 -> g_Wth [ATT][ENC] fp16
// ---------------------------------------------------------------------------
__global__ void k_transpose(const float* __restrict__ W) {
    __shared__ float t[32][33];
    int k0 = blockIdx.x * 32, n0 = blockIdx.y * 32;
    int x = threadIdx.x, y = threadIdx.y;   // 32 x 8
#pragma unroll
    for (int j = 0; j < 32; j += 8)
        t[y + j][x] = W[(size_t)(k0 + y + j) * ATT_ + n0 + x];
    __syncthreads();
#pragma unroll
    for (int j = 0; j < 32; j += 8)
        g_Wth[(size_t)(n0 + y + j) * ENC_ + k0 + x] = __float2half_rn(t[x][y + j]);
}

// ---------------------------------------------------------------------------
// Kernel 1: split-K att2 partials: g_c4[kz][b][a] = dec[b,k0:+128]@W_dec[k0:+128,a]
//   (+ biases on kz==0 slice).  No atomics, no zeroing.
// ---------------------------------------------------------------------------
__global__ void k_att2(const float* __restrict__ dec,
                       const float* __restrict__ W_dec,
                       const float* __restrict__ b_dec,
                       const float* __restrict__ b_enc) {
    int b0 = blockIdx.x * 4;
    int kz = blockIdx.y;
    int k0 = kz * 128;
    int tid = threadIdx.x;            // 512
    __shared__ float sdec[4][128];
    {
        int bb = tid >> 7, e = tid & 127;
        sdec[bb][e] = dec[(b0 + bb)*DEC_ + k0 + e];
    }
    __syncthreads();
    int a = tid;
    float acc[4] = {0.f, 0.f, 0.f, 0.f};
#pragma unroll 4
    for (int e = 0; e < 128; e++) {
        float w = W_dec[(size_t)(k0 + e)*ATT_ + a];
#pragma unroll
        for (int bb = 0; bb < 4; bb++) acc[bb] += sdec[bb][e] * w;
    }
    float bias = (kz == 0) ? (b_dec[a] + b_enc[a]) : 0.f;
    float* dst = g_c4 + (size_t)kz*B_*ATT_;
#pragma unroll
    for (int bb = 0; bb < 4; bb++)
        dst[(b0+bb)*ATT_ + a] = acc[bb] + bias;
}

// ---------------------------------------------------------------------------
// Kernel 2: fp16 mma.sync fused logits GEMM (R11, single full launch, UNTOUCHED)
//   CTA 64(M) x 256(N), BK=32, 4-stage, 8 warps x warptile 64x32, 2 CTAs/SM.
//   Epilogue writes g_attp[n_half][m] with plain stores (no atomics).
// ---------------------------------------------------------------------------
#define BM 64
#define BN 256
#define BK 32
#define NK (ENC_/BK)          // 64
#define NSTG 4
#define ROWB 80               // bytes per smem row (32 halves + 8 pad)
#define A_STG (BM*ROWB)       // 5120
#define B_STG (BN*ROWB)       // 20480
#define OFF_A    0
#define OFF_B    (NSTG*A_STG)                   // 20480
#define OFF_CS   (OFF_B + NSTG*B_STG)           // 102400
#define OFF_WS   (OFF_CS + 2*BN*4)              // 104448
#define OFF_SRED (OFF_WS + BN*4)                // 105472
#define SMEM_BYTES (OFF_SRED + BM*8*4)          // 107520

__device__ __forceinline__ void a_ldg(const float* __restrict__ enc, int m0, int kt,
                                      int tid, float4& l0, float4& l1) {
    int row = tid >> 2, c = tid & 3;
    const float* src = enc + (size_t)(m0 + row)*ENC_ + kt*BK + c*8;
    l0 = *(const float4*)src;
    l1 = *(const float4*)(src + 4);
}
__device__ __forceinline__ void a_sts(char* smem, int stg, int tid,
                                      const float4& l0, const float4& l1) {
    int row = tid >> 2, c = tid & 3;
    __half2 h[4];
    h[0] = __floats2half2_rn(l0.x, l0.y);
    h[1] = __floats2half2_rn(l0.z, l0.w);
    h[2] = __floats2half2_rn(l1.x, l1.y);
    h[3] = __floats2half2_rn(l1.z, l1.w);
    *(uint4*)(smem + OFF_A + stg*A_STG + row*ROWB + c*16) = *(uint4*)h;
}
__device__ __forceinline__ void b_load(uint32_t smb, int n0, int kt, int stg, int tid) {
    int k0 = kt * BK;
#pragma unroll
    for (int j = 0; j < 4; j++) {
        int i = tid + j*256;
        int row = i >> 2, c = i & 3;
        cp16(smb + OFF_B + stg*B_STG + row*ROWB + c*16,
             g_Wth + (size_t)(n0 + row)*ENC_ + k0 + c*8);
    }
}

__global__ void __launch_bounds__(256, 2)
k_gemm(const float* __restrict__ enc, const float* __restrict__ W_full) {
    extern __shared__ __align__(16) char smem[];
    uint32_t smb = smem_u32(smem);
    float* cs   = (float*)(smem + OFF_CS);    // [2][BN]
    float* ws   = (float*)(smem + OFF_WS);    // [BN]
    float* sred = (float*)(smem + OFF_SRED);  // [BM][8]

    int tid = threadIdx.x;
    int wn = tid >> 5, lane = tid & 31;       // 8 warps across N
    int g = lane >> 2, tg = lane & 3;
    int n0 = blockIdx.x * BN;                 // 0 or 256
    int m0 = blockIdx.y * BM;
    int bglob0 = m0 / P_;                     // tile spans <= 2 batches

    // epilogue constants (CTA's n-slice); sum 4 split-K partials of c
    ws[tid] = W_full[n0 + tid];
#pragma unroll
    for (int i = 0; i < 2; i++) {
        int bb = bglob0 + i; if (bb > B_-1) bb = B_-1;
        int idx = bb*ATT_ + n0 + tid;
        cs[i*BN + tid] = g_c4[idx] + g_c4[B_*ATT_ + idx]
                       + g_c4[2*B_*ATT_ + idx] + g_c4[3*B_*ATT_ + idx];
    }

    float acc[4][4][4];
#pragma unroll
    for (int a = 0; a < 4; a++)
#pragma unroll
        for (int b = 0; b < 4; b++)
#pragma unroll
            for (int c = 0; c < 4; c++) acc[a][b][c] = 0.f;

    // prologue: stages 0..2
#pragma unroll
    for (int s = 0; s < NSTG-1; s++) {
        float4 l0, l1;
        a_ldg(enc, m0, s, tid, l0, l1);
        a_sts(smem, s, tid, l0, l1);
        b_load(smb, n0, s, s, tid);
        CP_COMMIT();
    }

#pragma unroll 1
    for (int kt = 0; kt < NK; kt++) {
        CP_WAIT2();          // B stage kt landed (own view)
        __syncthreads();     // CTA visibility; iter kt-1 fully consumed
        bool pre = (kt + NSTG-1 < NK);
        int stg3 = (kt + NSTG-1) & (NSTG-1);
        float4 l0, l1;
        if (pre) {
            a_ldg(enc, m0, kt + NSTG-1, tid, l0, l1);  // long-latency, STS below
            b_load(smb, n0, kt + NSTG-1, stg3, tid);
        }
        CP_COMMIT();

        int stg = kt & (NSTG-1);
        const uint32_t* As = (const uint32_t*)(smem + OFF_A + stg*A_STG);  // stride 20 u32
        const uint32_t* Bs = (const uint32_t*)(smem + OFF_B + stg*B_STG);

#pragma unroll
        for (int kk = 0; kk < 2; kk++) {      // two k16 steps
            int kb = kk * 8;
            uint32_t af[4][4], bf[4][2];
#pragma unroll
            for (int ms = 0; ms < 4; ms++) {
                int r = ms*16 + g;
                af[ms][0] = As[ r     *20 + kb + tg    ];
                af[ms][1] = As[(r + 8)*20 + kb + tg    ];
                af[ms][2] = As[ r     *20 + kb + tg + 4];
                af[ms][3] = As[(r + 8)*20 + kb + tg + 4];
            }
#pragma unroll
            for (int ns = 0; ns < 4; ns++) {
                int n = wn*32 + ns*8 + g;
                bf[ns][0] = Bs[n*20 + kb + tg    ];
                bf[ns][1] = Bs[n*20 + kb + tg + 4];
            }
#pragma unroll
            for (int ms = 0; ms < 4; ms++)
#pragma unroll
                for (int ns = 0; ns < 4; ns++)
                    asm volatile(
                        "mma.sync.aligned.m16n8k16.row.col.f32.f16.f16.f32 "
                        "{%0,%1,%2,%3},{%4,%5,%6,%7},{%8,%9},{%0,%1,%2,%3};"
                        : "+f"(acc[ms][ns][0]), "+f"(acc[ms][ns][1]),
                          "+f"(acc[ms][ns][2]), "+f"(acc[ms][ns][3])
                        : "r"(af[ms][0]), "r"(af[ms][1]), "r"(af[ms][2]), "r"(af[ms][3]),
                          "r"(bf[ns][0]), "r"(bf[ns][1]));
            if (kk == 0 && pre) a_sts(smem, stg3, tid, l0, l1);
        }
    }

    // fused epilogue: +c, relu, *W_full, reduce over this CTA's 256 cols
#pragma unroll
    for (int ms = 0; ms < 4; ms++) {
#pragma unroll
        for (int h = 0; h < 2; h++) {
            int row = ms*16 + h*8 + g;
            int m = m0 + row;
            int bsel = (m / P_) - bglob0;
            const float* csr = cs + bsel*BN;
            float s = 0.f;
#pragma unroll
            for (int ns = 0; ns < 4; ns++) {
#pragma unroll
                for (int j = 0; j < 2; j++) {
                    int col = wn*32 + ns*8 + tg*2 + j;
                    float v = acc[ms][ns][h*2 + j] + csr[col];
                    s += fmaxf(v, 0.f) * ws[col];
                }
            }
            s += __shfl_xor_sync(0xffffffffu, s, 1);
            s += __shfl_xor_sync(0xffffffffu, s, 2);
            if (tg == 0) sred[row*8 + wn] = s;
        }
    }
    __syncthreads();
    if (tid < BM) {
        float s = 0.f;
#pragma unroll
        for (int w = 0; w < 8; w++) s += sred[tid*8 + w];
        g_attp[blockIdx.x*M_TOT + m0 + tid] = s;   // plain store, no atomic
    }
}

// ---------------------------------------------------------------------------
// Kernel 3: fused softmax (over P) + context GEMV (R11 version, 64.8us @ 81% HBM)
//   grid (2 e-halves, B); both halves recompute softmax, half 0 writes alpha.
// ---------------------------------------------------------------------------
__global__ void k_softctx(const float* __restrict__ enc,
                          float* __restrict__ alpha,
                          float* __restrict__ ctx) {
    int b = blockIdx.y, t = threadIdx.x;
    __shared__ float sm[256];
    __shared__ float sal[P_];
    float x = (t < P_) ? (g_attp[b*P_ + t] + g_attp[M_TOT + b*P_ + t]) : -1e30f;
    sm[t] = x; __syncthreads();
#pragma unroll
    for (int s = 128; s > 0; s >>= 1) {
        if (t < s) sm[t] = fmaxf(sm[t], sm[t+s]);
        __syncthreads();
    }
    float mx = sm[0]; __syncthreads();
    float e = (t < P_) ? __expf(x - mx) : 0.f;
    sm[t] = e; __syncthreads();
#pragma unroll
    for (int s = 128; s > 0; s >>= 1) {
        if (t < s) sm[t] += sm[t+s];
        __syncthreads();
    }
    float inv = 1.f / sm[0];
    float av = e * inv;
    if (t < P_) {
        sal[t] = av;
        if (blockIdx.x == 0) alpha[b*P_ + t] = av;
    }
    __syncthreads();

    int e0 = blockIdx.x * 1024 + t * 4;
    const float4* base = (const float4*)(enc + (size_t)b * P_ * ENC_ + e0);
    float4 acc = make_float4(0.f, 0.f, 0.f, 0.f);
#pragma unroll 4
    for (int p = 0; p < P_; p++) {
        float a = sal[p];
        float4 v = base[p * (ENC_/4)];
        acc.x += a*v.x; acc.y += a*v.y; acc.z += a*v.z; acc.w += a*v.w;
    }
    *(float4*)(ctx + (size_t)b*ENC_ + e0) = acc;
}

// ---------------------------------------------------------------------------
extern "C" void kernel_launch(void* const* d_in, const int* in_sizes, int n_in,
                              void* d_out, int out_size) {
    const float* enc    = (const float*)d_in[0];
    const float* dec    = (const float*)d_in[1];
    const float* W_enc  = (const float*)d_in[2];
    const float* b_enc  = (const float*)d_in[3];
    const float* W_dec  = (const float*)d_in[4];
    const float* b_dec  = (const float*)d_in[5];
    const float* W_full = (const float*)d_in[6];
    (void)in_sizes; (void)n_in; (void)out_size;

    float* out   = (float*)d_out;
    float* ctx   = out;               // [B, ENC]
    float* alpha = out + B_*ENC_;     // [B, P]

    static cudaStream_t s1;
    static cudaEvent_t evFork, evA;
    static int init = 0;
    if (!init) {
        cudaFuncSetAttribute(k_gemm, cudaFuncAttributeMaxDynamicSharedMemorySize, SMEM_BYTES);
        cudaStreamCreateWithFlags(&s1, cudaStreamNonBlocking);
        cudaEventCreateWithFlags(&evFork, cudaEventDisableTiming);
        cudaEventCreateWithFlags(&evA, cudaEventDisableTiming);
        init = 1;
    }

    // legal capture fork (R13-verified): att2 on s1 concurrent with transpose on s0.
    // Both finish before the GEMM; no co-residency with the hot kernel.
    cudaEventRecord(evFork, 0);
    cudaStreamWaitEvent(s1, evFork, 0);
    k_att2<<<dim3(B_/4, 4), 512, 0, s1>>>(dec, W_dec, b_dec, b_enc);
    cudaEventRecord(evA, s1);
    k_transpose<<<dim3(ENC_/32, ATT_/32), dim3(32, 8)>>>(W_enc);
    cudaStreamWaitEvent(0, evA, 0);   // join before gemm

    // GEMM: one untouched full launch (5.3 waves, best measured packing)
    k_gemm<<<dim3(ATT_/BN, M_TOT/BM), 256, SMEM_BYTES>>>(enc, W_full);
    // softmax+context: one launch after gemm (R11 version)
    k_softctx<<<dim3(2, B_), 256>>>(enc, alpha, ctx);
}

// round 16
// speedup vs baseline: 1.0847x; 1.0057x over previous
#include <cuda_runtime.h>
#include <cuda_fp16.h>
#include <cstdint>

#define B_   256
#define P_   196
#define ENC_ 2048
#define DEC_ 512
#define ATT_ 512
#define M_TOT (B_*P_)

// ---------------- scratch (__device__ globals; no cudaMalloc allowed) ------
__device__ float  g_c4[4*B_*ATT_];   // att2 split-K partials (write-only, no zero)
__device__ float  g_attp[2*M_TOT];   // per-n-half logit partials (write-only)
__device__ __half g_Wth[ATT_*ENC_];  // W_enc^T fp16: [n][k] (2 MB)

// ---------------------------------------------------------------------------
__device__ __forceinline__ uint32_t smem_u32(const void* p) {
    uint32_t a;
    asm("{ .reg .u64 t; cvta.to.shared.u64 t, %1; cvt.u32.u64 %0, t; }" : "=r"(a) : "l"(p));
    return a;
}
__device__ __forceinline__ void cp16(uint32_t dst, const void* src) {
    asm volatile("cp.async.cg.shared.global [%0], [%1], 16;" :: "r"(dst), "l"(src));
}
#define CP_COMMIT() asm volatile("cp.async.commit_group;" ::: "memory")
#define CP_WAIT2()  asm volatile("cp.async.wait_group 2;" ::: "memory")

// ---------------------------------------------------------------------------
// Kernel 0: transpose+convert W_enc [ENC,ATT] fp32 -> g_Wth [ATT][ENC] fp16
// ---------------------------------------------------------------------------
__global__ void k_transpose(const float* __restrict__ W) {
    __shared__ float t[32][33];
    int k0 = blockIdx.x * 32, n0 = blockIdx.y * 32;
    int x = threadIdx.x, y = threadIdx.y;   // 32 x 8
#pragma unroll
    for (int j = 0; j < 32; j += 8)
        t[y + j][x] = W[(size_t)(k0 + y + j) * ATT_ + n0 + x];
    __syncthreads();
#pragma unroll
    for (int j = 0; j < 32; j += 8)
        g_Wth[(size_t)(n0 + y + j) * ENC_ + k0 + x] = __float2half_rn(t[x][y + j]);
}

// ---------------------------------------------------------------------------
// Kernel 1: split-K att2 partials: g_c4[kz][b][a] = dec[b,k0:+128]@W_dec[k0:+128,a]
//   (+ biases on kz==0 slice).  No atomics, no zeroing.
// ---------------------------------------------------------------------------
__global__ void k_att2(const float* __restrict__ dec,
                       const float* __restrict__ W_dec,
                       const float* __restrict__ b_dec,
                       const float* __restrict__ b_enc) {
    int b0 = blockIdx.x * 4;
    int kz = blockIdx.y;
    int k0 = kz * 128;
    int tid = threadIdx.x;            // 512
    __shared__ float sdec[4][128];
    {
        int bb = tid >> 7, e = tid & 127;
        sdec[bb][e] = dec[(b0 + bb)*DEC_ + k0 + e];
    }
    __syncthreads();
    int a = tid;
    float acc[4] = {0.f, 0.f, 0.f, 0.f};
#pragma unroll 4
    for (int e = 0; e < 128; e++) {
        float w = W_dec[(size_t)(k0 + e)*ATT_ + a];
#pragma unroll
        for (int bb = 0; bb < 4; bb++) acc[bb] += sdec[bb][e] * w;
    }
    float bias = (kz == 0) ? (b_dec[a] + b_enc[a]) : 0.f;
    float* dst = g_c4 + (size_t)kz*B_*ATT_;
#pragma unroll
    for (int bb = 0; bb < 4; bb++)
        dst[(b0+bb)*ATT_ + a] = acc[bb] + bias;
}

// ---------------------------------------------------------------------------
// Kernel 2: fp16 mma.sync fused logits GEMM (single full launch)
//   CTA 64(M) x 256(N), BK=32, 4-stage, 8 warps x warptile 64x32, 2 CTAs/SM.
//   Epilogue writes g_attp[n_half][m] with plain stores (no atomics).
//   At ~93% of the sm_103 legacy mma.sync issue ceiling (rt~16/SMSP).
// ---------------------------------------------------------------------------
#define BM 64
#define BN 256
#define BK 32
#define NK (ENC_/BK)          // 64
#define NSTG 4
#define ROWB 80               // bytes per smem row (32 halves + 8 pad)
#define A_STG (BM*ROWB)       // 5120
#define B_STG (BN*ROWB)       // 20480
#define OFF_A    0
#define OFF_B    (NSTG*A_STG)                   // 20480
#define OFF_CS   (OFF_B + NSTG*B_STG)           // 102400
#define OFF_WS   (OFF_CS + 2*BN*4)              // 104448
#define OFF_SRED (OFF_WS + BN*4)                // 105472
#define SMEM_BYTES (OFF_SRED + BM*8*4)          // 107520

__device__ __forceinline__ void a_ldg(const float* __restrict__ enc, int m0, int kt,
                                      int tid, float4& l0, float4& l1) {
    int row = tid >> 2, c = tid & 3;
    const float* src = enc + (size_t)(m0 + row)*ENC_ + kt*BK + c*8;
    l0 = *(const float4*)src;
    l1 = *(const float4*)(src + 4);
}
__device__ __forceinline__ void a_sts(char* smem, int stg, int tid,
                                      const float4& l0, const float4& l1) {
    int row = tid >> 2, c = tid & 3;
    __half2 h[4];
    h[0] = __floats2half2_rn(l0.x, l0.y);
    h[1] = __floats2half2_rn(l0.z, l0.w);
    h[2] = __floats2half2_rn(l1.x, l1.y);
    h[3] = __floats2half2_rn(l1.z, l1.w);
    *(uint4*)(smem + OFF_A + stg*A_STG + row*ROWB + c*16) = *(uint4*)h;
}
__device__ __forceinline__ void b_load(uint32_t smb, int n0, int kt, int stg, int tid) {
    int k0 = kt * BK;
#pragma unroll
    for (int j = 0; j < 4; j++) {
        int i = tid + j*256;
        int row = i >> 2, c = i & 3;
        cp16(smb + OFF_B + stg*B_STG + row*ROWB + c*16,
             g_Wth + (size_t)(n0 + row)*ENC_ + k0 + c*8);
    }
}

__global__ void __launch_bounds__(256, 2)
k_gemm(const float* __restrict__ enc, const float* __restrict__ W_full) {
    extern __shared__ __align__(16) char smem[];
    uint32_t smb = smem_u32(smem);
    float* cs   = (float*)(smem + OFF_CS);    // [2][BN]
    float* ws   = (float*)(smem + OFF_WS);    // [BN]
    float* sred = (float*)(smem + OFF_SRED);  // [BM][8]

    int tid = threadIdx.x;
    int wn = tid >> 5, lane = tid & 31;       // 8 warps across N
    int g = lane >> 2, tg = lane & 3;
    int n0 = blockIdx.x * BN;                 // 0 or 256
    int m0 = blockIdx.y * BM;
    int bglob0 = m0 / P_;                     // tile spans <= 2 batches

    // epilogue constants (CTA's n-slice); sum 4 split-K partials of c
    ws[tid] = W_full[n0 + tid];
#pragma unroll
    for (int i = 0; i < 2; i++) {
        int bb = bglob0 + i; if (bb > B_-1) bb = B_-1;
        int idx = bb*ATT_ + n0 + tid;
        cs[i*BN + tid] = g_c4[idx] + g_c4[B_*ATT_ + idx]
                       + g_c4[2*B_*ATT_ + idx] + g_c4[3*B_*ATT_ + idx];
    }

    float acc[4][4][4];
#pragma unroll
    for (int a = 0; a < 4; a++)
#pragma unroll
        for (int b = 0; b < 4; b++)
#pragma unroll
            for (int c = 0; c < 4; c++) acc[a][b][c] = 0.f;

    // prologue: stages 0..2
#pragma unroll
    for (int s = 0; s < NSTG-1; s++) {
        float4 l0, l1;
        a_ldg(enc, m0, s, tid, l0, l1);
        a_sts(smem, s, tid, l0, l1);
        b_load(smb, n0, s, s, tid);
        CP_COMMIT();
    }

#pragma unroll 1
    for (int kt = 0; kt < NK; kt++) {
        CP_WAIT2();          // B stage kt landed (own view)
        __syncthreads();     // CTA visibility; iter kt-1 fully consumed
        bool pre = (kt + NSTG-1 < NK);
        int stg3 = (kt + NSTG-1) & (NSTG-1);
        float4 l0, l1;
        if (pre) {
            a_ldg(enc, m0, kt + NSTG-1, tid, l0, l1);  // long-latency, STS below
            b_load(smb, n0, kt + NSTG-1, stg3, tid);
        }
        CP_COMMIT();

        int stg = kt & (NSTG-1);
        const uint32_t* As = (const uint32_t*)(smem + OFF_A + stg*A_STG);  // stride 20 u32
        const uint32_t* Bs = (const uint32_t*)(smem + OFF_B + stg*B_STG);

#pragma unroll
        for (int kk = 0; kk < 2; kk++) {      // two k16 steps
            int kb = kk * 8;
            uint32_t af[4][4], bf[4][2];
#pragma unroll
            for (int ms = 0; ms < 4; ms++) {
                int r = ms*16 + g;
                af[ms][0] = As[ r     *20 + kb + tg    ];
                af[ms][1] = As[(r + 8)*20 + kb + tg    ];
                af[ms][2] = As[ r     *20 + kb + tg + 4];
                af[ms][3] = As[(r + 8)*20 + kb + tg + 4];
            }
#pragma unroll
            for (int ns = 0; ns < 4; ns++) {
                int n = wn*32 + ns*8 + g;
                bf[ns][0] = Bs[n*20 + kb + tg    ];
                bf[ns][1] = Bs[n*20 + kb + tg + 4];
            }
#pragma unroll
            for (int ms = 0; ms < 4; ms++)
#pragma unroll
                for (int ns = 0; ns < 4; ns++)
                    asm volatile(
                        "mma.sync.aligned.m16n8k16.row.col.f32.f16.f16.f32 "
                        "{%0,%1,%2,%3},{%4,%5,%6,%7},{%8,%9},{%0,%1,%2,%3};"
                        : "+f"(acc[ms][ns][0]), "+f"(acc[ms][ns][1]),
                          "+f"(acc[ms][ns][2]), "+f"(acc[ms][ns][3])
                        : "r"(af[ms][0]), "r"(af[ms][1]), "r"(af[ms][2]), "r"(af[ms][3]),
                          "r"(bf[ns][0]), "r"(bf[ns][1]));
            if (kk == 0 && pre) a_sts(smem, stg3, tid, l0, l1);
        }
    }

    // fused epilogue: +c, relu, *W_full, reduce over this CTA's 256 cols
#pragma unroll
    for (int ms = 0; ms < 4; ms++) {
#pragma unroll
        for (int h = 0; h < 2; h++) {
            int row = ms*16 + h*8 + g;
            int m = m0 + row;
            int bsel = (m / P_) - bglob0;
            const float* csr = cs + bsel*BN;
            float s = 0.f;
#pragma unroll
            for (int ns = 0; ns < 4; ns++) {
#pragma unroll
                for (int j = 0; j < 2; j++) {
                    int col = wn*32 + ns*8 + tg*2 + j;
                    float v = acc[ms][ns][h*2 + j] + csr[col];
                    s += fmaxf(v, 0.f) * ws[col];
                }
            }
            s += __shfl_xor_sync(0xffffffffu, s, 1);
            s += __shfl_xor_sync(0xffffffffu, s, 2);
            if (tg == 0) sred[row*8 + wn] = s;
        }
    }
    __syncthreads();
    if (tid < BM) {
        float s = 0.f;
#pragma unroll
        for (int w = 0; w < 8; w++) s += sred[tid*8 + w];
        g_attp[blockIdx.x*M_TOT + m0 + tid] = s;   // plain store, no atomic
    }
}

// ---------------------------------------------------------------------------
// Kernel 3: fused softmax (over P) + context GEMV (fp32 enc, 81% of HBM peak)
//   grid (2 e-halves, B); both halves recompute softmax, half 0 writes alpha.
// ---------------------------------------------------------------------------
__global__ void k_softctx(const float* __restrict__ enc,
                          float* __restrict__ alpha,
                          float* __restrict__ ctx) {
    int b = blockIdx.y, t = threadIdx.x;
    __shared__ float sm[256];
    __shared__ float sal[P_];
    float x = (t < P_) ? (g_attp[b*P_ + t] + g_attp[M_TOT + b*P_ + t]) : -1e30f;
    sm[t] = x; __syncthreads();
#pragma unroll
    for (int s = 128; s > 0; s >>= 1) {
        if (t < s) sm[t] = fmaxf(sm[t], sm[t+s]);
        __syncthreads();
    }
    float mx = sm[0]; __syncthreads();
    float e = (t < P_) ? __expf(x - mx) : 0.f;
    sm[t] = e; __syncthreads();
#pragma unroll
    for (int s = 128; s > 0; s >>= 1) {
        if (t < s) sm[t] += sm[t+s];
        __syncthreads();
    }
    float inv = 1.f / sm[0];
    float av = e * inv;
    if (t < P_) {
        sal[t] = av;
        if (blockIdx.x == 0) alpha[b*P_ + t] = av;
    }
    __syncthreads();

    int e0 = blockIdx.x * 1024 + t * 4;
    const float4* base = (const float4*)(enc + (size_t)b * P_ * ENC_ + e0);
    float4 acc = make_float4(0.f, 0.f, 0.f, 0.f);
#pragma unroll 4
    for (int p = 0; p < P_; p++) {
        float a = sal[p];
        float4 v = base[p * (ENC_/4)];
        acc.x += a*v.x; acc.y += a*v.y; acc.z += a*v.z; acc.w += a*v.w;
    }
    *(float4*)(ctx + (size_t)b*ENC_ + e0) = acc;
}

// ---------------------------------------------------------------------------
extern "C" void kernel_launch(void* const* d_in, const int* in_sizes, int n_in,
                              void* d_out, int out_size) {
    const float* enc    = (const float*)d_in[0];
    const float* dec    = (const float*)d_in[1];
    const float* W_enc  = (const float*)d_in[2];
    const float* b_enc  = (const float*)d_in[3];
    const float* W_dec  = (const float*)d_in[4];
    const float* b_dec  = (const float*)d_in[5];
    const float* W_full = (const float*)d_in[6];
    // d_in[7] = b_full: softmax shift-invariant, att not an output -> unused
    (void)in_sizes; (void)n_in; (void)out_size;

    float* out   = (float*)d_out;
    float* ctx   = out;               // [B, ENC]
    float* alpha = out + B_*ENC_;     // [B, P]

    static int smem_set = 0;
    if (!smem_set) {
        cudaFuncSetAttribute(k_gemm, cudaFuncAttributeMaxDynamicSharedMemorySize, SMEM_BYTES);
        smem_set = 1;
    }

    k_transpose<<<dim3(ENC_/32, ATT_/32), dim3(32, 8)>>>(W_enc);
    k_att2     <<<dim3(B_/4, 4), 512>>>(dec, W_dec, b_dec, b_enc);
    k_gemm     <<<dim3(ATT_/BN, M_TOT/BM), 256, SMEM_BYTES>>>(enc, W_full);
    k_softctx  <<<dim3(2, B_), 256>>>(enc, alpha, ctx);
}